// round 15
// baseline (speedup 1.0000x reference)
#include <cuda_runtime.h>

#define BB    512
#define VV    50257
#define TT    2048
#define TOPK  50
#define NT    512
#define NWRP  16
#define CAPW  256
#define CAPF  (NWRP * CAPW)      // 4096, flat capacity (fallback)
#define CAP2  256
#define NBIN  2048
#define MASKW 1571
#define MASKP 1600
#define T0    8.0f
#define KBASE 0xC1000000u        // fkey(8.0f)

typedef unsigned long long u64;

struct Scr {
    float sval[TOPK];
    int   sidx[TOPK];
    float wred[NWRP];
    float zcor[NWRP];
    int   ct[NWRP];
    u64   gkey[2];
    unsigned mrawKey, K;
    float Z, Mref, M0, Zk, invt;
    int   ncand, nc2, fb, m;
};

__device__ __forceinline__ unsigned fkey(float x) {
    unsigned u = __float_as_uint(x);
    return (u & 0x80000000u) ? ~u : (u | 0x80000000u);
}
__device__ __forceinline__ float fdec(unsigned k) {
    return __uint_as_float((k & 0x80000000u) ? (k ^ 0x80000000u) : ~k);
}
__device__ __forceinline__ float penal(float x, float rp, float invrp) {
    return x < 0.f ? x * rp : x * invrp;
}
__device__ __forceinline__ u64 mkkey(float x, int v) {
    return ((u64)fkey(x) << 32) | (u64)(0xFFFFFFFFu - (unsigned)v);
}
__device__ __forceinline__ void pushf(u64* ck, int* pnc, float x, int v) {
    int pos = atomicAdd(pnc, 1);
    if (pos < CAPF) ck[pos] = mkkey(x, v);
}
__device__ __forceinline__ u64 wmax64(u64 v) {
    #pragma unroll
    for (int off = 16; off; off >>= 1) {
        u64 o = __shfl_xor_sync(0xffffffffu, v, off);
        if (o > v) v = o;
    }
    return v;
}

// occ 3 -> 42 regs available: buys a 4-wide independent LDG pipeline (MLP 4).
// Wave penalty of occ3 (444 slots, 1.15 ragged wave) == occ4's existing
// 4-vs-3 CTA/SM imbalance (1.156x), so this costs nothing structurally.
__global__ void __launch_bounds__(NT, 3)
decode_kernel(const float* __restrict__ logits,
              const int*   __restrict__ prev,
              const float* __restrict__ randu,
              const float* __restrict__ tempp,
              const float* __restrict__ toppp,
              const float* __restrict__ rpp,
              float*  probsF, double* probsD,
              long long* idx64, float* idxF, double* idxD)
{
    __shared__ unsigned mask[MASKP];
    __shared__ u64 ckey[CAPF];                 // 16 warp slices of CAPW (flat in fallback)
    __shared__ __align__(16) int hist[NBIN];   // aliased as wsel (u64[16*50]) in backup
    __shared__ u64 ckey2[CAP2];
    __shared__ int gsum[NT];
    __shared__ int wcntA[NWRP];
    __shared__ Scr S;

    const int b    = blockIdx.x;
    const int tid  = threadIdx.x;
    const int lane = tid & 31;
    const int wrp  = tid >> 5;
    const int wbase = wrp * CAPW;

    const int p     = (4 - (b & 3)) & 3;
    const int nvec  = (VV - p) >> 2;
    const int vtail = p + (nvec << 2);

    const float* lrow = logits + (long long)b * VV;
    float*  orowF = probsF ? probsF + (long long)b * VV : nullptr;
    double* orowD = probsD ? probsD + (long long)b * VV : nullptr;

    if (orowD)
        for (int v = tid; v < VV; v += NT) orowD[v] = 0.0;

    for (int i = tid; i < MASKP; i += NT) mask[i] = 0u;
    if (tid < NWRP) wcntA[tid] = 0;
    if (tid == 0) { S.ncand = 0; S.nc2 = 0; S.fb = 0; S.mrawKey = 0u; }
    __syncthreads();

    // ---- penalty bitmask ----
    const int* prow = prev + (long long)b * TT;
    for (int i = tid; i < TT; i += NT) {
        unsigned tok = (unsigned)prow[i];
        if (tok < (unsigned)VV)
            atomicOr(&mask[tok >> 5], 1u << (tok & 31));
    }
    __syncthreads();

    const float rp    = __ldg(rpp);
    const float invrp = 1.f / rp;

    // ===== single full pass, 4-wide software pipeline (MLP 4) =====
    // zero-store + Z + per-warp candidate push, no mask interaction.
    float zsA = 0.f, zsB = 0.f, zsC = 0.f, zsD = 0.f;
    const float4 z4 = make_float4(0.f, 0.f, 0.f, 0.f);
    int k = tid;
    for (; k + 3 * NT < nvec; k += 4 * NT) {
        const int va = p + 4 * k;
        const int vb = va + 4 * NT;
        const int vc = vb + 4 * NT;
        const int vd = vc + 4 * NT;
        float4 A = __ldg((const float4*)(lrow + va));
        float4 B = __ldg((const float4*)(lrow + vb));
        float4 C = __ldg((const float4*)(lrow + vc));
        float4 D = __ldg((const float4*)(lrow + vd));
        if (orowF) {
            *(float4*)(orowF + va) = z4;
            *(float4*)(orowF + vb) = z4;
            *(float4*)(orowF + vc) = z4;
            *(float4*)(orowF + vd) = z4;
        }
        zsA += __expf(A.x) + __expf(A.y) + __expf(A.z) + __expf(A.w);
        zsB += __expf(B.x) + __expf(B.y) + __expf(B.z) + __expf(B.w);
        zsC += __expf(C.x) + __expf(C.y) + __expf(C.z) + __expf(C.w);
        zsD += __expf(D.x) + __expf(D.y) + __expf(D.z) + __expf(D.w);
        float gA = fmaxf(fmaxf(A.x, A.y), fmaxf(A.z, A.w));
        float gB = fmaxf(fmaxf(B.x, B.y), fmaxf(B.z, B.w));
        float gC = fmaxf(fmaxf(C.x, C.y), fmaxf(C.z, C.w));
        float gD = fmaxf(fmaxf(D.x, D.y), fmaxf(D.z, D.w));
        if (gA >= T0) {
            int nb = (int)(A.x >= T0) + (int)(A.y >= T0) + (int)(A.z >= T0) + (int)(A.w >= T0);
            int pos = atomicAdd(&wcntA[wrp], nb);
            if (A.x >= T0) { if (pos < CAPW) ckey[wbase + pos] = mkkey(A.x, va);     pos++; }
            if (A.y >= T0) { if (pos < CAPW) ckey[wbase + pos] = mkkey(A.y, va + 1); pos++; }
            if (A.z >= T0) { if (pos < CAPW) ckey[wbase + pos] = mkkey(A.z, va + 2); pos++; }
            if (A.w >= T0) { if (pos < CAPW) ckey[wbase + pos] = mkkey(A.w, va + 3); pos++; }
        }
        if (gB >= T0) {
            int nb = (int)(B.x >= T0) + (int)(B.y >= T0) + (int)(B.z >= T0) + (int)(B.w >= T0);
            int pos = atomicAdd(&wcntA[wrp], nb);
            if (B.x >= T0) { if (pos < CAPW) ckey[wbase + pos] = mkkey(B.x, vb);     pos++; }
            if (B.y >= T0) { if (pos < CAPW) ckey[wbase + pos] = mkkey(B.y, vb + 1); pos++; }
            if (B.z >= T0) { if (pos < CAPW) ckey[wbase + pos] = mkkey(B.z, vb + 2); pos++; }
            if (B.w >= T0) { if (pos < CAPW) ckey[wbase + pos] = mkkey(B.w, vb + 3); pos++; }
        }
        if (gC >= T0) {
            int nb = (int)(C.x >= T0) + (int)(C.y >= T0) + (int)(C.z >= T0) + (int)(C.w >= T0);
            int pos = atomicAdd(&wcntA[wrp], nb);
            if (C.x >= T0) { if (pos < CAPW) ckey[wbase + pos] = mkkey(C.x, vc);     pos++; }
            if (C.y >= T0) { if (pos < CAPW) ckey[wbase + pos] = mkkey(C.y, vc + 1); pos++; }
            if (C.z >= T0) { if (pos < CAPW) ckey[wbase + pos] = mkkey(C.z, vc + 2); pos++; }
            if (C.w >= T0) { if (pos < CAPW) ckey[wbase + pos] = mkkey(C.w, vc + 3); pos++; }
        }
        if (gD >= T0) {
            int nb = (int)(D.x >= T0) + (int)(D.y >= T0) + (int)(D.z >= T0) + (int)(D.w >= T0);
            int pos = atomicAdd(&wcntA[wrp], nb);
            if (D.x >= T0) { if (pos < CAPW) ckey[wbase + pos] = mkkey(D.x, vd);     pos++; }
            if (D.y >= T0) { if (pos < CAPW) ckey[wbase + pos] = mkkey(D.y, vd + 1); pos++; }
            if (D.z >= T0) { if (pos < CAPW) ckey[wbase + pos] = mkkey(D.z, vd + 2); pos++; }
            if (D.w >= T0) { if (pos < CAPW) ckey[wbase + pos] = mkkey(D.w, vd + 3); pos++; }
        }
    }
    for (; k < nvec; k += NT) {
        const int v0 = p + 4 * k;
        float4 A = __ldg((const float4*)(lrow + v0));
        if (orowF) *(float4*)(orowF + v0) = z4;
        zsA += __expf(A.x) + __expf(A.y) + __expf(A.z) + __expf(A.w);
        float gA = fmaxf(fmaxf(A.x, A.y), fmaxf(A.z, A.w));
        if (gA >= T0) {
            int nb = (int)(A.x >= T0) + (int)(A.y >= T0) + (int)(A.z >= T0) + (int)(A.w >= T0);
            int pos = atomicAdd(&wcntA[wrp], nb);
            if (A.x >= T0) { if (pos < CAPW) ckey[wbase + pos] = mkkey(A.x, v0);     pos++; }
            if (A.y >= T0) { if (pos < CAPW) ckey[wbase + pos] = mkkey(A.y, v0 + 1); pos++; }
            if (A.z >= T0) { if (pos < CAPW) ckey[wbase + pos] = mkkey(A.z, v0 + 2); pos++; }
            if (A.w >= T0) { if (pos < CAPW) ckey[wbase + pos] = mkkey(A.w, v0 + 3); pos++; }
        }
    }
    // scalar tails (prefix + remainder, <= 6 elements total)
    for (int v = tid; v < p; v += NT) {
        float x = __ldg(lrow + v);
        if (orowF) orowF[v] = 0.f;
        zsA += __expf(x);
        if (x >= T0) {
            int pos = atomicAdd(&wcntA[wrp], 1);
            if (pos < CAPW) ckey[wbase + pos] = mkkey(x, v);
        }
    }
    for (int v = vtail + tid; v < VV; v += NT) {
        float x = __ldg(lrow + v);
        if (orowF) orowF[v] = 0.f;
        zsA += __expf(x);
        if (x >= T0) {
            int pos = atomicAdd(&wcntA[wrp], 1);
            if (pos < CAPW) ckey[wbase + pos] = mkkey(x, v);
        }
    }
    float zs = (zsA + zsB) + (zsC + zsD);
    #pragma unroll
    for (int off = 16; off; off >>= 1)
        zs += __shfl_xor_sync(0xffffffffu, zs, off);
    if (lane == 0) S.wred[wrp] = zs;
    __syncthreads();

    // ---- pen-scan: exact Z correction over masked tokens ----
    float zc = 0.f;
    for (int w = tid; w < MASKW; w += NT) {
        unsigned bits = mask[w];
        while (bits) {
            int bpos = __ffs(bits) - 1;
            bits &= bits - 1;
            int tok = (w << 5) + bpos;
            float x = __ldg(lrow + tok);
            zc += __expf(penal(x, rp, invrp)) - __expf(x);
        }
    }
    #pragma unroll
    for (int off = 16; off; off >>= 1)
        zc += __shfl_xor_sync(0xffffffffu, zc, off);
    if (lane == 0) S.zcor[wrp] = zc;
    // zero histogram while waiting
    for (int i = tid; i < NBIN; i += NT) hist[i] = 0;
    __syncthreads();

    if (tid == 0) {
        float Zr = 0.f, Zc = 0.f;
        int fb = 0;
        #pragma unroll
        for (int j = 0; j < NWRP; j++) {
            Zr += S.wred[j];
            Zc += S.zcor[j];
            if (wcntA[j] > CAPW) fb = 1;        // slice overflow
        }
        float Zfin = Zr + Zc;
        if (!(Zfin > 0.f) || !isfinite(Zfin)) fb = 1;  // overflow/NaN anywhere
        S.Z = Zfin; S.Mref = 0.f; S.fb = fb;
    }
    __syncthreads();

    // ---- penalty-adjust slices + completeness count + histogram ----
    if (!S.fb) {
        const int myc = min(wcntA[wrp], CAPW);
        int ct = 0;
        for (int i = lane; i < myc; i += 32) {
            u64 c = ckey[wbase + i];
            unsigned low = (unsigned)(c & 0xFFFFFFFFull);
            int vidx = (int)(0xFFFFFFFFu - low);
            unsigned key = (unsigned)(c >> 32);
            if ((mask[vidx >> 5] >> (vidx & 31)) & 1u) {
                float x = penal(fdec(key), rp, invrp);
                key = fkey(x);
                ckey[wbase + i] = ((u64)key << 32) | (u64)low;
            }
            if (key >= KBASE) {
                ct++;
                int bin = (int)((key >> 13) - (KBASE >> 13));
                atomicAdd(&hist[min(bin, NBIN - 1)], 1);
            }
        }
        #pragma unroll
        for (int off = 16; off; off >>= 1)
            ct += __shfl_xor_sync(0xffffffffu, ct, off);
        if (lane == 0) S.ct[wrp] = ct;
    }
    __syncthreads();
    if (tid == 0 && !S.fb) {
        int t = 0;
        #pragma unroll
        for (int j = 0; j < NWRP; j++) t += S.ct[j];
        if (t < TOPK) S.fb = 1;                 // candidate set incomplete
    }
    __syncthreads();

    // ---- exact fallback (essentially never) ----
    if (S.fb) {
        float fm = -3.4e38f;
        for (int kk2 = tid; kk2 < nvec; kk2 += NT) {
            const int v0 = p + 4 * kk2;
            float4 X = __ldg((const float4*)(lrow + v0));
            unsigned bits = __funnelshift_r(mask[v0 >> 5], mask[(v0 >> 5) + 1], v0 & 31) & 0xFu;
            if (bits & 1u) X.x = penal(X.x, rp, invrp);
            if (bits & 2u) X.y = penal(X.y, rp, invrp);
            if (bits & 4u) X.z = penal(X.z, rp, invrp);
            if (bits & 8u) X.w = penal(X.w, rp, invrp);
            fm = fmaxf(fm, fmaxf(fmaxf(X.x, X.y), fmaxf(X.z, X.w)));
        }
        for (int v = tid; v < p; v += NT) {
            float x = __ldg(lrow + v);
            if ((mask[v >> 5] >> (v & 31)) & 1u) x = penal(x, rp, invrp);
            fm = fmaxf(fm, x);
        }
        for (int v = vtail + tid; v < VV; v += NT) {
            float x = __ldg(lrow + v);
            if ((mask[v >> 5] >> (v & 31)) & 1u) x = penal(x, rp, invrp);
            fm = fmaxf(fm, x);
        }
        #pragma unroll
        for (int off = 16; off; off >>= 1)
            fm = fmaxf(fm, __shfl_xor_sync(0xffffffffu, fm, off));
        if (lane == 0) atomicMax(&S.mrawKey, fkey(fm));
        __syncthreads();
        const float Mf = fdec(S.mrawKey);

        float z2 = 0.f;
        for (int kk2 = tid; kk2 < nvec; kk2 += NT) {
            const int v0 = p + 4 * kk2;
            float4 X = __ldg((const float4*)(lrow + v0));
            unsigned bits = __funnelshift_r(mask[v0 >> 5], mask[(v0 >> 5) + 1], v0 & 31) & 0xFu;
            if (bits & 1u) X.x = penal(X.x, rp, invrp);
            if (bits & 2u) X.y = penal(X.y, rp, invrp);
            if (bits & 4u) X.z = penal(X.z, rp, invrp);
            if (bits & 8u) X.w = penal(X.w, rp, invrp);
            z2 += __expf(X.x - Mf) + __expf(X.y - Mf) + __expf(X.z - Mf) + __expf(X.w - Mf);
        }
        for (int v = tid; v < p; v += NT) {
            float x = __ldg(lrow + v);
            if ((mask[v >> 5] >> (v & 31)) & 1u) x = penal(x, rp, invrp);
            z2 += __expf(x - Mf);
        }
        for (int v = vtail + tid; v < VV; v += NT) {
            float x = __ldg(lrow + v);
            if ((mask[v >> 5] >> (v & 31)) & 1u) x = penal(x, rp, invrp);
            z2 += __expf(x - Mf);
        }
        #pragma unroll
        for (int off = 16; off; off >>= 1)
            z2 += __shfl_xor_sync(0xffffffffu, z2, off);
        if (lane == 0) S.wred[wrp] = z2;
        __syncthreads();
        if (tid == 0) {
            float gz = 0.f;
            #pragma unroll
            for (int j = 0; j < NWRP; j++) gz += S.wred[j];
            S.Z = gz; S.Mref = Mf;
        }

        float delta = 9.f;
        for (int it = 0; it < 9; ++it) {
            __syncthreads();
            if (tid == 0) S.ncand = 0;
            __syncthreads();
            const float t = Mf - delta;
            for (int kk2 = tid; kk2 < nvec; kk2 += NT) {
                const int v0 = p + 4 * kk2;
                float4 X = __ldg((const float4*)(lrow + v0));
                unsigned bits = __funnelshift_r(mask[v0 >> 5], mask[(v0 >> 5) + 1], v0 & 31) & 0xFu;
                if (bits & 1u) X.x = penal(X.x, rp, invrp);
                if (bits & 2u) X.y = penal(X.y, rp, invrp);
                if (bits & 4u) X.z = penal(X.z, rp, invrp);
                if (bits & 8u) X.w = penal(X.w, rp, invrp);
                if (X.x >= t) pushf(ckey, &S.ncand, X.x, v0);
                if (X.y >= t) pushf(ckey, &S.ncand, X.y, v0 + 1);
                if (X.z >= t) pushf(ckey, &S.ncand, X.z, v0 + 2);
                if (X.w >= t) pushf(ckey, &S.ncand, X.w, v0 + 3);
            }
            for (int v = tid; v < p; v += NT) {
                float x = __ldg(lrow + v);
                if ((mask[v >> 5] >> (v & 31)) & 1u) x = penal(x, rp, invrp);
                if (x >= t) pushf(ckey, &S.ncand, x, v);
            }
            for (int v = vtail + tid; v < VV; v += NT) {
                float x = __ldg(lrow + v);
                if ((mask[v >> 5] >> (v & 31)) & 1u) x = penal(x, rp, invrp);
                if (x >= t) pushf(ckey, &S.ncand, x, v);
            }
            __syncthreads();
            int c = S.ncand;
            if (c >= TOPK && c <= CAPF) break;
            delta = (c < TOPK) ? delta * 2.f : delta * 0.5f;
        }
        const int n = min(S.ncand, CAPF);
        const int kk = min(TOPK, n);
        // heavy flat sweep (rare path)
        if (wrp == 0) {
            for (int r = 0; r < kk; ++r) {
                u64 best = 0ull;
                for (int i = lane; i < n; i += 32) {
                    u64 c = ckey[i];
                    if (c > best) best = c;
                }
                best = wmax64(best);
                for (int i = lane; i < n; i += 32)
                    if (ckey[i] == best) ckey[i] = 0ull;
                if (lane == 0) {
                    S.sval[r] = fdec((unsigned)(best >> 32));
                    S.sidx[r] = (int)(0xFFFFFFFFu - (unsigned)(best & 0xFFFFFFFFull));
                }
                __syncwarp();
            }
        }
        if (tid == 0) S.m = kk;    // stash kk
        __syncthreads();
    } else {
        // ---- rank-50 threshold via suffix scan of histogram ----
        {
            int t4 = hist[4 * tid] + hist[4 * tid + 1] + hist[4 * tid + 2] + hist[4 * tid + 3];
            gsum[tid] = t4;
        }
        __syncthreads();
        if (tid < 32) {
            int s = 0;
            #pragma unroll
            for (int j = 0; j < 16; j++) s += gsum[tid * 16 + j];
            int suf = s;
            #pragma unroll
            for (int off = 1; off < 32; off <<= 1) {
                int o = __shfl_down_sync(0xffffffffu, suf, off);
                if (tid + off < 32) suf += o;
            }
            unsigned ball = __ballot_sync(0xffffffffu, suf >= TOPK);
            int g = 31 - __clz(ball);
            int above = __shfl_sync(0xffffffffu, suf, (g + 1) & 31);
            if (g == 31) above = 0;

            int s2 = (lane < 16) ? gsum[g * 16 + lane] : 0;
            int suf2 = s2;
            #pragma unroll
            for (int off = 1; off < 32; off <<= 1) {
                int o = __shfl_down_sync(0xffffffffu, suf2, off);
                if (lane + off < 32) suf2 += o;
            }
            unsigned ball2 = __ballot_sync(0xffffffffu, (above + suf2) >= TOPK);
            int l2 = 31 - __clz(ball2);
            int above2 = above + ((l2 >= 15) ? 0 : __shfl_sync(0xffffffffu, suf2, l2 + 1));
            if (tid == 0) {
                int gb = (g * 16 + l2) * 4;
                int acc = above2;
                int B = gb;
                for (int j = 3; j >= 0; --j) {
                    acc += hist[gb + j];
                    if (acc >= TOPK) { B = gb + j; break; }
                }
                S.K = KBASE + ((unsigned)B << 13);
            }
        }
        __syncthreads();

        // ---- compact candidates >= K ----
        {
            const unsigned K = S.K;
            const int myc = min(wcntA[wrp], CAPW);
            for (int i = lane; i < myc; i += 32) {
                u64 c = ckey[wbase + i];
                if ((unsigned)(c >> 32) >= K) {
                    int q = atomicAdd(&S.nc2, 1);
                    if (q < CAP2) ckey2[q] = c;
                }
            }
        }
        __syncthreads();
        const int nc2 = S.nc2;

        if (nc2 <= CAP2) {
            // warp-0 exact sort of <=256 compacted candidates
            if (wrp == 0) {
                u64 q[8];
                #pragma unroll
                for (int j = 0; j < 8; ++j) {
                    int i = lane + 32 * j;
                    q[j] = (i < nc2) ? ckey2[i] : 0ull;
                }
                for (int r = 0; r < TOPK; ++r) {
                    u64 loc = 0;
                    #pragma unroll
                    for (int j = 0; j < 8; ++j) if (q[j] > loc) loc = q[j];
                    u64 wm = wmax64(loc);
                    if (lane == 0) {
                        S.sval[r] = fdec((unsigned)(wm >> 32));
                        S.sidx[r] = (int)(0xFFFFFFFFu - (unsigned)(wm & 0xFFFFFFFFull));
                    }
                    #pragma unroll
                    for (int j = 0; j < 8; ++j) if (q[j] == wm) q[j] = 0;
                }
            }
        } else {
            // backup: per-slice partial top-50 + merge (hist space as wsel)
            u64* wsel = (u64*)hist;
            for (int i = tid; i < NWRP * TOPK; i += NT) wsel[i] = 0ull;
            __syncthreads();
            {
                const int myc = min(wcntA[wrp], CAPW);
                u64 q[8];
                #pragma unroll
                for (int j = 0; j < 8; ++j) {
                    int i = lane + 32 * j;
                    q[j] = (i < myc) ? ckey[wbase + i] : 0ull;
                }
                for (int r = 0; r < TOPK; ++r) {
                    u64 loc = 0;
                    #pragma unroll
                    for (int j = 0; j < 8; ++j) if (q[j] > loc) loc = q[j];
                    u64 wm = wmax64(loc);
                    if (wm == 0ull) break;
                    if (lane == 0) wsel[wrp * TOPK + r] = wm;
                    #pragma unroll
                    for (int j = 0; j < 8; ++j) if (q[j] == wm) { q[j] = 0; break; }
                }
            }
            __syncthreads();
            if (wrp == 0) {
                u64 q[25];
                #pragma unroll
                for (int j = 0; j < 25; ++j) q[j] = wsel[lane + 32 * j];
                for (int r = 0; r < TOPK; ++r) {
                    u64 loc = 0;
                    #pragma unroll
                    for (int j = 0; j < 25; ++j) if (q[j] > loc) loc = q[j];
                    u64 wm = wmax64(loc);
                    if (lane == 0) {
                        S.sval[r] = fdec((unsigned)(wm >> 32));
                        S.sidx[r] = (int)(0xFFFFFFFFu - (unsigned)(wm & 0xFFFFFFFFull));
                    }
                    #pragma unroll
                    for (int j = 0; j < 25; ++j) if (q[j] == wm) q[j] = 0;
                }
            }
        }
        if (tid == 0) S.m = TOPK;
        __syncthreads();
    }

    const int kk = S.m;
    __syncthreads();

    // ---- thread 0: top-p cutoff, Zk ----
    if (tid == 0) {
        const float Z    = S.Z;
        const float Mref = S.Mref;
        const float topp = __ldg(toppp);
        const float temp = fmaxf(__ldg(tempp), 1e-5f);
        const float invt = 1.f / temp;

        float c = 0.f; int cnt = 0;
        for (int kx = 0; kx < kk; ++kx) {
            c += expf(S.sval[kx] - Mref) / Z;
            if (c <= topp) cnt++; else break;
        }
        int mm = cnt < 1 ? 1 : cnt;
        if (mm > kk) mm = kk;

        const float M0 = S.sval[0];
        float Zk = 0.f;
        for (int kx = 0; kx < mm; ++kx) Zk += expf((S.sval[kx] - M0) * invt);

        S.m = mm; S.M0 = M0; S.Zk = Zk; S.invt = invt;
        S.gkey[0] = 0ull; S.gkey[1] = 0ull;
    }
    __syncthreads();

    // ---- parallel Gumbel argmax over kept tokens ----
    const int   mm   = S.m;
    const float M0   = S.M0;
    const float Zk   = S.Zk;
    const float invt = S.invt;

    if (tid < 64) {
        u64 key = 0ull;
        if (tid < mm) {
            float pk = expf((S.sval[tid] - M0) * invt) / Zk;
            float u  = __ldg(randu + (long long)b * VV + S.sidx[tid]);
            float r  = pk / (-logf(u));
            key = ((u64)fkey(r) << 32) |
                  (u64)(0xFFFFFFFFu - (unsigned)S.sidx[tid]);
        }
        #pragma unroll
        for (int off = 16; off; off >>= 1) {
            u64 o = __shfl_xor_sync(0xffffffffu, key, off);
            if (o > key) key = o;
        }
        if (lane == 0) S.gkey[wrp] = key;
    }
    __syncthreads();

    if (tid == 0) {
        u64 best = S.gkey[0] > S.gkey[1] ? S.gkey[0] : S.gkey[1];
        int besti = (int)(0xFFFFFFFFu - (unsigned)(best & 0xFFFFFFFFull));
        if (idx64) idx64[b] = (long long)besti;
        if (idxF)  idxF[b]  = (float)besti;
        if (idxD)  idxD[b]  = (double)besti;
    }

    // ---- scatter the mm nonzero probabilities (row zeroed earlier this CTA) ----
    if (tid < mm) {
        float pk = expf((S.sval[tid] - M0) * invt) / Zk;
        if (orowF) orowF[S.sidx[tid]] = pk;
        else if (orowD) orowD[S.sidx[tid]] = (double)pk;
    }
}

extern "C" void kernel_launch(void* const* d_in, const int* in_sizes, int n_in,
                              void* d_out, int out_size)
{
    const float* logits = (const float*)d_in[0];
    const int*   prev   = (const int*)d_in[1];
    const float* randu  = (const float*)d_in[2];
    const float* temp   = (const float*)d_in[3];
    const float* topp   = (const float*)d_in[4];
    const float* rp     = (const float*)d_in[5];

    float*  probsF = nullptr; double* probsD = nullptr;
    long long* idx64 = nullptr; float* idxF = nullptr; double* idxD = nullptr;

    const long long BV = (long long)BB * VV;
    const long long oz = (long long)out_size;

    if (oz == BB + BV) {
        // tuple concat, float32 elements (idx cast to float) — the passing layout
        idxF = (float*)d_out; probsF = (float*)d_out + BB;
    } else if (oz == 2 * BB + BV) {
        idx64 = (long long*)d_out; probsF = (float*)d_out + 2 * BB;
    } else if (oz == BB + BV / 2) {
        idx64 = (long long*)d_out; probsF = (float*)((long long*)d_out + BB);
    } else if (oz == BV) {
        probsF = (float*)d_out;
    } else if (oz == BB) {
        idx64 = (long long*)d_out;
    } else if (oz == 8LL * BB + 4LL * BV) {
        idx64 = (long long*)d_out; probsF = (float*)((char*)d_out + 8LL * BB);
    } else {
        idxF = (float*)d_out; probsF = (float*)d_out + BB;
    }

    decode_kernel<<<BB, NT>>>(logits, prev, randu, temp, topp, rp,
                              probsF, probsD, idx64, idxF, idxD);
}

// round 16
// speedup vs baseline: 1.1926x; 1.1926x over previous
#include <cuda_runtime.h>

#define BB    512
#define ZB    80                 // zero-fill CTAs (BB+ZB = 592 = 148*4, one wave)
#define VV    50257
#define TT    2048
#define TOPK  50
#define NT    512
#define NWRP  16
#define CAPW  256
#define CAPF  (NWRP * CAPW)
#define CAP2  256
#define NBIN  2048
#define MASKW 1571
#define MASKP 1600
#define T0    8.0f
#define KBASE 0xC1000000u        // fkey(8.0f)

typedef unsigned long long u64;

// cross-kernel scratch (allowed: __device__ globals, no allocation)
__device__ float g_pv[BB * TOPK];
__device__ int   g_pi[BB * TOPK];
__device__ int   g_m[BB];
__device__ int   g_bi[BB];

struct Scr {
    float sval[TOPK];
    int   sidx[TOPK];
    float wred[NWRP];
    float zcor[NWRP];
    int   ct[NWRP];
    u64   gkey[2];
    unsigned mrawKey, K;
    float Z, Mref, M0, Zk, invt;
    int   ncand, nc2, fb, m;
};

__device__ __forceinline__ unsigned fkey(float x) {
    unsigned u = __float_as_uint(x);
    return (u & 0x80000000u) ? ~u : (u | 0x80000000u);
}
__device__ __forceinline__ float fdec(unsigned k) {
    return __uint_as_float((k & 0x80000000u) ? (k ^ 0x80000000u) : ~k);
}
__device__ __forceinline__ float penal(float x, float rp, float invrp) {
    return x < 0.f ? x * rp : x * invrp;
}
__device__ __forceinline__ u64 mkkey(float x, int v) {
    return ((u64)fkey(x) << 32) | (u64)(0xFFFFFFFFu - (unsigned)v);
}
__device__ __forceinline__ void pushf(u64* ck, int* pnc, float x, int v) {
    int pos = atomicAdd(pnc, 1);
    if (pos < CAPF) ck[pos] = mkkey(x, v);
}
__device__ __forceinline__ u64 wmax64(u64 v) {
    #pragma unroll
    for (int off = 16; off; off >>= 1) {
        u64 o = __shfl_xor_sync(0xffffffffu, v, off);
        if (o > v) v = o;
    }
    return v;
}

__global__ void __launch_bounds__(NT, 4)
decode_kernel(const float* __restrict__ logits,
              const int*   __restrict__ prev,
              const float* __restrict__ randu,
              const float* __restrict__ tempp,
              const float* __restrict__ toppp,
              const float* __restrict__ rpp,
              char* outbase, long long zbytes)
{
    __shared__ unsigned mask[MASKP];
    __shared__ u64 ckey[CAPF];
    __shared__ __align__(16) int hist[NBIN];
    __shared__ u64 ckey2[CAP2];
    __shared__ int gsum[NT];
    __shared__ int wcntA[NWRP];
    __shared__ Scr S;

    const int tid  = threadIdx.x;

    // ===== zero-fill CTAs: memset the output buffer, run concurrently =====
    if (blockIdx.x >= BB) {
        const long long zb = blockIdx.x - BB;
        const long long n16 = zbytes >> 4;
        uint4* o = (uint4*)outbase;
        const uint4 z = make_uint4(0u, 0u, 0u, 0u);
        for (long long i = zb * NT + tid; i < n16; i += (long long)ZB * NT)
            o[i] = z;
        if (zb == 0)
            for (long long i = (n16 << 4) + tid; i < zbytes; i += NT)
                outbase[i] = 0;
        return;
    }

    const int b    = blockIdx.x;
    const int lane = tid & 31;
    const int wrp  = tid >> 5;
    const int wbase = wrp * CAPW;

    const int p     = (4 - (b & 3)) & 3;
    const int nvec  = (VV - p) >> 2;
    const int vtail = p + (nvec << 2);

    const float* lrow = logits + (long long)b * VV;

    for (int i = tid; i < MASKP; i += NT) mask[i] = 0u;
    if (tid < NWRP) wcntA[tid] = 0;
    if (tid == 0) { S.ncand = 0; S.nc2 = 0; S.fb = 0; S.mrawKey = 0u; }
    __syncthreads();

    // ---- penalty bitmask ----
    const int* prow = prev + (long long)b * TT;
    for (int i = tid; i < TT; i += NT) {
        unsigned tok = (unsigned)prow[i];
        if (tok < (unsigned)VV)
            atomicOr(&mask[tok >> 5], 1u << (tok & 31));
    }
    __syncthreads();

    const float rp    = __ldg(rpp);
    const float invrp = 1.f / rp;

    // ===== single read pass: Z + per-warp-counter candidate push =====
    float zs = 0.f;
    #pragma unroll 2
    for (int k = tid; k < nvec; k += NT) {
        const int v0 = p + 4 * k;
        float4 X = __ldg((const float4*)(lrow + v0));
        zs += __expf(X.x) + __expf(X.y) + __expf(X.z) + __expf(X.w);
        int nb = (int)(X.x >= T0) + (int)(X.y >= T0) + (int)(X.z >= T0) + (int)(X.w >= T0);
        if (nb) {
            int pos = atomicAdd(&wcntA[wrp], nb);
            if (X.x >= T0) { if (pos < CAPW) ckey[wbase + pos] = mkkey(X.x, v0);     pos++; }
            if (X.y >= T0) { if (pos < CAPW) ckey[wbase + pos] = mkkey(X.y, v0 + 1); pos++; }
            if (X.z >= T0) { if (pos < CAPW) ckey[wbase + pos] = mkkey(X.z, v0 + 2); pos++; }
            if (X.w >= T0) { if (pos < CAPW) ckey[wbase + pos] = mkkey(X.w, v0 + 3); pos++; }
        }
    }
    for (int v = tid; v < p; v += NT) {
        float x = __ldg(lrow + v);
        zs += __expf(x);
        if (x >= T0) {
            int pos = atomicAdd(&wcntA[wrp], 1);
            if (pos < CAPW) ckey[wbase + pos] = mkkey(x, v);
        }
    }
    for (int v = vtail + tid; v < VV; v += NT) {
        float x = __ldg(lrow + v);
        zs += __expf(x);
        if (x >= T0) {
            int pos = atomicAdd(&wcntA[wrp], 1);
            if (pos < CAPW) ckey[wbase + pos] = mkkey(x, v);
        }
    }
    #pragma unroll
    for (int off = 16; off; off >>= 1)
        zs += __shfl_xor_sync(0xffffffffu, zs, off);
    if (lane == 0) S.wred[wrp] = zs;
    __syncthreads();

    // ---- pen-scan: exact Z correction over masked tokens ----
    float zc = 0.f;
    for (int w = tid; w < MASKW; w += NT) {
        unsigned bits = mask[w];
        while (bits) {
            int bpos = __ffs(bits) - 1;
            bits &= bits - 1;
            int tok = (w << 5) + bpos;
            float x = __ldg(lrow + tok);
            zc += __expf(penal(x, rp, invrp)) - __expf(x);
        }
    }
    #pragma unroll
    for (int off = 16; off; off >>= 1)
        zc += __shfl_xor_sync(0xffffffffu, zc, off);
    if (lane == 0) S.zcor[wrp] = zc;
    for (int i = tid; i < NBIN; i += NT) hist[i] = 0;
    __syncthreads();

    if (tid == 0) {
        float Zr = 0.f, Zc = 0.f;
        int fb = 0;
        #pragma unroll
        for (int j = 0; j < NWRP; j++) {
            Zr += S.wred[j];
            Zc += S.zcor[j];
            if (wcntA[j] > CAPW) fb = 1;
        }
        float Zfin = Zr + Zc;
        if (!(Zfin > 0.f) || !isfinite(Zfin)) fb = 1;
        S.Z = Zfin; S.Mref = 0.f; S.fb = fb;
    }
    __syncthreads();

    // ---- penalty-adjust slices + completeness count + histogram ----
    if (!S.fb) {
        const int myc = min(wcntA[wrp], CAPW);
        int ct = 0;
        for (int i = lane; i < myc; i += 32) {
            u64 c = ckey[wbase + i];
            unsigned low = (unsigned)(c & 0xFFFFFFFFull);
            int vidx = (int)(0xFFFFFFFFu - low);
            unsigned key = (unsigned)(c >> 32);
            if ((mask[vidx >> 5] >> (vidx & 31)) & 1u) {
                float x = penal(fdec(key), rp, invrp);
                key = fkey(x);
                ckey[wbase + i] = ((u64)key << 32) | (u64)low;
            }
            if (key >= KBASE) {
                ct++;
                int bin = (int)((key >> 13) - (KBASE >> 13));
                atomicAdd(&hist[min(bin, NBIN - 1)], 1);
            }
        }
        #pragma unroll
        for (int off = 16; off; off >>= 1)
            ct += __shfl_xor_sync(0xffffffffu, ct, off);
        if (lane == 0) S.ct[wrp] = ct;
    }
    __syncthreads();
    if (tid == 0 && !S.fb) {
        int t = 0;
        #pragma unroll
        for (int j = 0; j < NWRP; j++) t += S.ct[j];
        if (t < TOPK) S.fb = 1;
    }
    __syncthreads();

    // ---- exact fallback (essentially never) ----
    if (S.fb) {
        float fm = -3.4e38f;
        for (int k = tid; k < nvec; k += NT) {
            const int v0 = p + 4 * k;
            float4 X = __ldg((const float4*)(lrow + v0));
            unsigned bits = __funnelshift_r(mask[v0 >> 5], mask[(v0 >> 5) + 1], v0 & 31) & 0xFu;
            if (bits & 1u) X.x = penal(X.x, rp, invrp);
            if (bits & 2u) X.y = penal(X.y, rp, invrp);
            if (bits & 4u) X.z = penal(X.z, rp, invrp);
            if (bits & 8u) X.w = penal(X.w, rp, invrp);
            fm = fmaxf(fm, fmaxf(fmaxf(X.x, X.y), fmaxf(X.z, X.w)));
        }
        for (int v = tid; v < p; v += NT) {
            float x = __ldg(lrow + v);
            if ((mask[v >> 5] >> (v & 31)) & 1u) x = penal(x, rp, invrp);
            fm = fmaxf(fm, x);
        }
        for (int v = vtail + tid; v < VV; v += NT) {
            float x = __ldg(lrow + v);
            if ((mask[v >> 5] >> (v & 31)) & 1u) x = penal(x, rp, invrp);
            fm = fmaxf(fm, x);
        }
        #pragma unroll
        for (int off = 16; off; off >>= 1)
            fm = fmaxf(fm, __shfl_xor_sync(0xffffffffu, fm, off));
        if (lane == 0) atomicMax(&S.mrawKey, fkey(fm));
        __syncthreads();
        const float Mf = fdec(S.mrawKey);

        float z2 = 0.f;
        for (int k = tid; k < nvec; k += NT) {
            const int v0 = p + 4 * k;
            float4 X = __ldg((const float4*)(lrow + v0));
            unsigned bits = __funnelshift_r(mask[v0 >> 5], mask[(v0 >> 5) + 1], v0 & 31) & 0xFu;
            if (bits & 1u) X.x = penal(X.x, rp, invrp);
            if (bits & 2u) X.y = penal(X.y, rp, invrp);
            if (bits & 4u) X.z = penal(X.z, rp, invrp);
            if (bits & 8u) X.w = penal(X.w, rp, invrp);
            z2 += __expf(X.x - Mf) + __expf(X.y - Mf) + __expf(X.z - Mf) + __expf(X.w - Mf);
        }
        for (int v = tid; v < p; v += NT) {
            float x = __ldg(lrow + v);
            if ((mask[v >> 5] >> (v & 31)) & 1u) x = penal(x, rp, invrp);
            z2 += __expf(x - Mf);
        }
        for (int v = vtail + tid; v < VV; v += NT) {
            float x = __ldg(lrow + v);
            if ((mask[v >> 5] >> (v & 31)) & 1u) x = penal(x, rp, invrp);
            z2 += __expf(x - Mf);
        }
        #pragma unroll
        for (int off = 16; off; off >>= 1)
            z2 += __shfl_xor_sync(0xffffffffu, z2, off);
        if (lane == 0) S.wred[wrp] = z2;
        __syncthreads();
        if (tid == 0) {
            float gz = 0.f;
            #pragma unroll
            for (int j = 0; j < NWRP; j++) gz += S.wred[j];
            S.Z = gz; S.Mref = Mf;
        }

        float delta = 9.f;
        for (int it = 0; it < 9; ++it) {
            __syncthreads();
            if (tid == 0) S.ncand = 0;
            __syncthreads();
            const float t = Mf - delta;
            for (int k = tid; k < nvec; k += NT) {
                const int v0 = p + 4 * k;
                float4 X = __ldg((const float4*)(lrow + v0));
                unsigned bits = __funnelshift_r(mask[v0 >> 5], mask[(v0 >> 5) + 1], v0 & 31) & 0xFu;
                if (bits & 1u) X.x = penal(X.x, rp, invrp);
                if (bits & 2u) X.y = penal(X.y, rp, invrp);
                if (bits & 4u) X.z = penal(X.z, rp, invrp);
                if (bits & 8u) X.w = penal(X.w, rp, invrp);
                if (X.x >= t) pushf(ckey, &S.ncand, X.x, v0);
                if (X.y >= t) pushf(ckey, &S.ncand, X.y, v0 + 1);
                if (X.z >= t) pushf(ckey, &S.ncand, X.z, v0 + 2);
                if (X.w >= t) pushf(ckey, &S.ncand, X.w, v0 + 3);
            }
            for (int v = tid; v < p; v += NT) {
                float x = __ldg(lrow + v);
                if ((mask[v >> 5] >> (v & 31)) & 1u) x = penal(x, rp, invrp);
                if (x >= t) pushf(ckey, &S.ncand, x, v);
            }
            for (int v = vtail + tid; v < VV; v += NT) {
                float x = __ldg(lrow + v);
                if ((mask[v >> 5] >> (v & 31)) & 1u) x = penal(x, rp, invrp);
                if (x >= t) pushf(ckey, &S.ncand, x, v);
            }
            __syncthreads();
            int c = S.ncand;
            if (c >= TOPK && c <= CAPF) break;
            delta = (c < TOPK) ? delta * 2.f : delta * 0.5f;
        }
        const int n = min(S.ncand, CAPF);
        const int kkf = min(TOPK, n);
        if (wrp == 0) {
            for (int r = 0; r < kkf; ++r) {
                u64 best = 0ull;
                for (int i = lane; i < n; i += 32) {
                    u64 c = ckey[i];
                    if (c > best) best = c;
                }
                best = wmax64(best);
                for (int i = lane; i < n; i += 32)
                    if (ckey[i] == best) ckey[i] = 0ull;
                if (lane == 0) {
                    S.sval[r] = fdec((unsigned)(best >> 32));
                    S.sidx[r] = (int)(0xFFFFFFFFu - (unsigned)(best & 0xFFFFFFFFull));
                }
                __syncwarp();
            }
        }
        if (tid == 0) S.m = kkf;
        __syncthreads();
    } else {
        // ---- rank-50 threshold via suffix scan of histogram ----
        {
            int t4 = hist[4 * tid] + hist[4 * tid + 1] + hist[4 * tid + 2] + hist[4 * tid + 3];
            gsum[tid] = t4;
        }
        __syncthreads();
        if (tid < 32) {
            int s = 0;
            #pragma unroll
            for (int j = 0; j < 16; j++) s += gsum[tid * 16 + j];
            int suf = s;
            #pragma unroll
            for (int off = 1; off < 32; off <<= 1) {
                int o = __shfl_down_sync(0xffffffffu, suf, off);
                if (tid + off < 32) suf += o;
            }
            unsigned ball = __ballot_sync(0xffffffffu, suf >= TOPK);
            int g = 31 - __clz(ball);
            int above = __shfl_sync(0xffffffffu, suf, (g + 1) & 31);
            if (g == 31) above = 0;

            int s2 = (lane < 16) ? gsum[g * 16 + lane] : 0;
            int suf2 = s2;
            #pragma unroll
            for (int off = 1; off < 32; off <<= 1) {
                int o = __shfl_down_sync(0xffffffffu, suf2, off);
                if (lane + off < 32) suf2 += o;
            }
            unsigned ball2 = __ballot_sync(0xffffffffu, (above + suf2) >= TOPK);
            int l2 = 31 - __clz(ball2);
            int above2 = above + ((l2 >= 15) ? 0 : __shfl_sync(0xffffffffu, suf2, l2 + 1));
            if (tid == 0) {
                int gb = (g * 16 + l2) * 4;
                int acc = above2;
                int B = gb;
                for (int j = 3; j >= 0; --j) {
                    acc += hist[gb + j];
                    if (acc >= TOPK) { B = gb + j; break; }
                }
                S.K = KBASE + ((unsigned)B << 13);
            }
        }
        __syncthreads();

        // ---- compact candidates >= K ----
        {
            const unsigned K = S.K;
            const int myc = min(wcntA[wrp], CAPW);
            for (int i = lane; i < myc; i += 32) {
                u64 c = ckey[wbase + i];
                if ((unsigned)(c >> 32) >= K) {
                    int q = atomicAdd(&S.nc2, 1);
                    if (q < CAP2) ckey2[q] = c;
                }
            }
        }
        __syncthreads();
        const int nc2 = S.nc2;

        if (nc2 <= CAP2) {
            if (wrp == 0) {
                u64 q[8];
                #pragma unroll
                for (int j = 0; j < 8; ++j) {
                    int i = lane + 32 * j;
                    q[j] = (i < nc2) ? ckey2[i] : 0ull;
                }
                for (int r = 0; r < TOPK; ++r) {
                    u64 loc = 0;
                    #pragma unroll
                    for (int j = 0; j < 8; ++j) if (q[j] > loc) loc = q[j];
                    u64 wm = wmax64(loc);
                    if (lane == 0) {
                        S.sval[r] = fdec((unsigned)(wm >> 32));
                        S.sidx[r] = (int)(0xFFFFFFFFu - (unsigned)(wm & 0xFFFFFFFFull));
                    }
                    #pragma unroll
                    for (int j = 0; j < 8; ++j) if (q[j] == wm) q[j] = 0;
                }
            }
        } else {
            u64* wsel = (u64*)hist;
            for (int i = tid; i < NWRP * TOPK; i += NT) wsel[i] = 0ull;
            __syncthreads();
            {
                const int myc = min(wcntA[wrp], CAPW);
                u64 q[8];
                #pragma unroll
                for (int j = 0; j < 8; ++j) {
                    int i = lane + 32 * j;
                    q[j] = (i < myc) ? ckey[wbase + i] : 0ull;
                }
                for (int r = 0; r < TOPK; ++r) {
                    u64 loc = 0;
                    #pragma unroll
                    for (int j = 0; j < 8; ++j) if (q[j] > loc) loc = q[j];
                    u64 wm = wmax64(loc);
                    if (wm == 0ull) break;
                    if (lane == 0) wsel[wrp * TOPK + r] = wm;
                    #pragma unroll
                    for (int j = 0; j < 8; ++j) if (q[j] == wm) { q[j] = 0; break; }
                }
            }
            __syncthreads();
            if (wrp == 0) {
                u64 q[25];
                #pragma unroll
                for (int j = 0; j < 25; ++j) q[j] = wsel[lane + 32 * j];
                for (int r = 0; r < TOPK; ++r) {
                    u64 loc = 0;
                    #pragma unroll
                    for (int j = 0; j < 25; ++j) if (q[j] > loc) loc = q[j];
                    u64 wm = wmax64(loc);
                    if (lane == 0) {
                        S.sval[r] = fdec((unsigned)(wm >> 32));
                        S.sidx[r] = (int)(0xFFFFFFFFu - (unsigned)(wm & 0xFFFFFFFFull));
                    }
                    #pragma unroll
                    for (int j = 0; j < 25; ++j) if (q[j] == wm) q[j] = 0;
                }
            }
        }
        if (tid == 0) S.m = TOPK;
        __syncthreads();
    }

    const int kk = S.m;
    __syncthreads();

    // ---- thread 0: top-p cutoff, Zk ----
    if (tid == 0) {
        const float Z    = S.Z;
        const float Mref = S.Mref;
        const float topp = __ldg(toppp);
        const float temp = fmaxf(__ldg(tempp), 1e-5f);
        const float invt = 1.f / temp;

        float c = 0.f; int cnt = 0;
        for (int kx = 0; kx < kk; ++kx) {
            c += expf(S.sval[kx] - Mref) / Z;
            if (c <= topp) cnt++; else break;
        }
        int mm = cnt < 1 ? 1 : cnt;
        if (mm > kk) mm = kk;

        const float M0 = S.sval[0];
        float Zk = 0.f;
        for (int kx = 0; kx < mm; ++kx) Zk += expf((S.sval[kx] - M0) * invt);

        S.m = mm; S.M0 = M0; S.Zk = Zk; S.invt = invt;
        S.gkey[0] = 0ull; S.gkey[1] = 0ull;
    }
    __syncthreads();

    // ---- parallel Gumbel argmax over kept tokens ----
    const int   mm   = S.m;
    const float M0   = S.M0;
    const float Zk   = S.Zk;
    const float invt = S.invt;

    if (tid < 64) {
        u64 key = 0ull;
        if (tid < mm) {
            float pk = expf((S.sval[tid] - M0) * invt) / Zk;
            float u  = __ldg(randu + (long long)b * VV + S.sidx[tid]);
            float r  = pk / (-logf(u));
            key = ((u64)fkey(r) << 32) |
                  (u64)(0xFFFFFFFFu - (unsigned)S.sidx[tid]);
        }
        #pragma unroll
        for (int off = 16; off; off >>= 1) {
            u64 o = __shfl_xor_sync(0xffffffffu, key, off);
            if (o > key) key = o;
        }
        if (lane == 0) S.gkey[wrp] = key;
    }
    __syncthreads();

    // ---- write results to scratch (scatter kernel finishes the job) ----
    if (tid == 0) {
        u64 best = S.gkey[0] > S.gkey[1] ? S.gkey[0] : S.gkey[1];
        g_bi[b] = (int)(0xFFFFFFFFu - (unsigned)(best & 0xFFFFFFFFull));
        g_m[b]  = mm;
    }
    if (tid < mm) {
        float pk = expf((S.sval[tid] - M0) * invt) / Zk;
        g_pv[b * TOPK + tid] = pk;
        g_pi[b * TOPK + tid] = S.sidx[tid];
    }
}

__global__ void __launch_bounds__(64)
scatter_kernel(float* probsF, double* probsD,
               long long* idx64, float* idxF, double* idxD)
{
    const int b = blockIdx.x;
    const int t = threadIdx.x;
    const int mm = g_m[b];
    if (t < mm) {
        float pk = g_pv[b * TOPK + t];
        int   vi = g_pi[b * TOPK + t];
        if (probsF) probsF[(long long)b * VV + vi] = pk;
        else if (probsD) probsD[(long long)b * VV + vi] = (double)pk;
    }
    if (t == 0) {
        int besti = g_bi[b];
        if (idx64) idx64[b] = (long long)besti;
        if (idxF)  idxF[b]  = (float)besti;
        if (idxD)  idxD[b]  = (double)besti;
    }
}

extern "C" void kernel_launch(void* const* d_in, const int* in_sizes, int n_in,
                              void* d_out, int out_size)
{
    const float* logits = (const float*)d_in[0];
    const int*   prev   = (const int*)d_in[1];
    const float* randu  = (const float*)d_in[2];
    const float* temp   = (const float*)d_in[3];
    const float* topp   = (const float*)d_in[4];
    const float* rp     = (const float*)d_in[5];

    float*  probsF = nullptr; double* probsD = nullptr;
    long long* idx64 = nullptr; float* idxF = nullptr; double* idxD = nullptr;

    const long long BV = (long long)BB * VV;
    const long long oz = (long long)out_size;
    long long zbytes;

    if (oz == BB + BV) {
        // tuple concat, float32 elements (idx cast to float) — the passing layout
        idxF = (float*)d_out; probsF = (float*)d_out + BB;
        zbytes = 4 * oz;
    } else if (oz == 2 * BB + BV) {
        idx64 = (long long*)d_out; probsF = (float*)d_out + 2 * BB;
        zbytes = 4 * oz;
    } else if (oz == BB + BV / 2) {
        idx64 = (long long*)d_out; probsF = (float*)((long long*)d_out + BB);
        zbytes = 8 * oz;
    } else if (oz == BV) {
        probsF = (float*)d_out;
        zbytes = 4 * oz;
    } else if (oz == BB) {
        idx64 = (long long*)d_out;
        zbytes = 8 * oz;
    } else if (oz == 8LL * BB + 4LL * BV) {
        idx64 = (long long*)d_out; probsF = (float*)((char*)d_out + 8LL * BB);
        zbytes = oz;
    } else {
        idxF = (float*)d_out; probsF = (float*)d_out + BB;
        zbytes = 4 * oz;
    }

    decode_kernel<<<BB + ZB, NT>>>(logits, prev, randu, temp, topp, rp,
                                   (char*)d_out, zbytes);
    scatter_kernel<<<BB, 64>>>(probsF, probsD, idx64, idxF, idxD);
}